// round 8
// baseline (speedup 1.0000x reference)
#include <cuda_runtime.h>
#include <cuda_bf16.h>
#include <math.h>
#include <cstdint>

#define N_NODES 20000
#define N_EDGES 640000
#define D 256
#define N_RELS 8
#define N_BASES 4
#define KA 2560              // physical A: [T_hi(1024)|T_lo(1024)|x_hi(256)|x_lo(256)]
#define KTOT 3840            // virtual K (B layout): [W_hi|W_hi|W_lo | loop_hi|loop_hi|loop_lo]
#define KSEG 1280            // 3 K-segments

// ---------------- device scratch (allocation-free rule) ----------------
__device__ __align__(16) __nv_bfloat16 g_A3[(size_t)N_NODES * KA];    // 102MB
__device__ __align__(16) __nv_bfloat16 g_B2[(size_t)256 * KTOT];      // 1.9MB [out-col n][k]
__device__ float g_agg[(size_t)N_NODES * 256];                        // 20MB
__device__ int g_hist[N_NODES];
__device__ int g_cursor[N_NODES];
__device__ int g_start[N_NODES + 1];
__device__ uint32_t g_edges[N_EDGES];   // packed src | (type<<15)

__device__ __forceinline__ float gelu_exact(float x) {
    return 0.5f * x * (1.0f + erff(x * 0.70710678118654752440f));
}
__device__ __forceinline__ uint32_t smem_to_u32(const void* p) {
    uint32_t a;
    asm("{ .reg .u64 t; cvta.to.shared.u64 t, %1; cvt.u32.u64 %0, t; }" : "=r"(a) : "l"(p));
    return a;
}
__device__ __forceinline__ void cp_async16(uint32_t dst, const void* src, int src_sz) {
    asm volatile("cp.async.cg.shared.global [%0], [%1], 16, %2;" :: "r"(dst), "l"(src), "r"(src_sz) : "memory");
}
__device__ __forceinline__ void cp_async_commit() { asm volatile("cp.async.commit_group;" ::: "memory"); }
template <int N> __device__ __forceinline__ void cp_async_wait() {
    asm volatile("cp.async.wait_group %0;" :: "n"(N) : "memory");
}
__device__ __forceinline__ void ldsm_x4(uint32_t& r0, uint32_t& r1, uint32_t& r2, uint32_t& r3, uint32_t addr) {
    asm volatile("ldmatrix.sync.aligned.m8n8.x4.shared.b16 {%0,%1,%2,%3}, [%4];"
                 : "=r"(r0), "=r"(r1), "=r"(r2), "=r"(r3) : "r"(addr));
}
__device__ __forceinline__ void mma16816(float* d, uint32_t a0, uint32_t a1, uint32_t a2, uint32_t a3,
                                         uint32_t b0, uint32_t b1) {
    asm volatile("mma.sync.aligned.m16n8k16.row.col.f32.bf16.bf16.f32 "
                 "{%0,%1,%2,%3}, {%4,%5,%6,%7}, {%8,%9}, {%0,%1,%2,%3};"
                 : "+f"(d[0]), "+f"(d[1]), "+f"(d[2]), "+f"(d[3])
                 : "r"(a0), "r"(a1), "r"(a2), "r"(a3), "r"(b0), "r"(b1));
}
__device__ __forceinline__ void red_add_v2(float* addr, float a, float b) {
    asm volatile("red.global.add.v2.f32 [%0], {%1,%2};" :: "l"(addr), "f"(a), "f"(b) : "memory");
}

// ---------------------------------------------------------------------------
// Zero: g_agg (1.28M float4) + g_hist
// ---------------------------------------------------------------------------
__global__ void __launch_bounds__(256) zero_kernel() {
    int gid = blockIdx.x * blockDim.x + threadIdx.x;
    if (gid < N_NODES * 64) ((float4*)g_agg)[gid] = make_float4(0.f, 0.f, 0.f, 0.f);
    if (gid < N_NODES) g_hist[gid] = 0;
}

// 4 edges per thread (N_EDGES % 4 == 0)
__global__ void __launch_bounds__(256) hist_kernel(const int* __restrict__ dst) {
    int g4 = (blockIdx.x * blockDim.x + threadIdx.x) * 4;
    if (g4 >= N_EDGES) return;
    int4 d = *(const int4*)(dst + g4);
    atomicAdd(&g_hist[d.x], 1);
    atomicAdd(&g_hist[d.y], 1);
    atomicAdd(&g_hist[d.z], 1);
    atomicAdd(&g_hist[d.w], 1);
}

// single block 1024 threads, 20 bins each
__global__ void __launch_bounds__(1024) scan_kernel() {
    __shared__ int sm[1024];
    int t = threadIdx.x;
    int base = t * 20;
    int cnt[20];
    int s = 0;
#pragma unroll
    for (int i = 0; i < 20; i++) {
        int idx = base + i;
        int c = (idx < N_NODES) ? g_hist[idx] : 0;
        cnt[i] = c; s += c;
    }
    sm[t] = s;
    __syncthreads();
    for (int off = 1; off < 1024; off <<= 1) {
        int v = (t >= off) ? sm[t - off] : 0;
        __syncthreads();
        sm[t] += v;
        __syncthreads();
    }
    int run = (t > 0) ? sm[t - 1] : 0;
#pragma unroll
    for (int i = 0; i < 20; i++) {
        int idx = base + i;
        if (idx < N_NODES) {
            g_start[idx] = run;
            g_cursor[idx] = run;
            run += cnt[i];
        }
    }
    if (t == 1023) g_start[N_NODES] = sm[1023];
}

// 4 edges per thread
__global__ void __launch_bounds__(256) reorder_kernel(const int* __restrict__ src,
                                                      const int* __restrict__ dst,
                                                      const int* __restrict__ et) {
    int g4 = (blockIdx.x * blockDim.x + threadIdx.x) * 4;
    if (g4 >= N_EDGES) return;
    int4 s = *(const int4*)(src + g4);
    int4 d = *(const int4*)(dst + g4);
    int4 t = *(const int4*)(et + g4);
    int p0 = atomicAdd(&g_cursor[d.x], 1);
    int p1 = atomicAdd(&g_cursor[d.y], 1);
    int p2 = atomicAdd(&g_cursor[d.z], 1);
    int p3 = atomicAdd(&g_cursor[d.w], 1);
    g_edges[p0] = (uint32_t)s.x | ((uint32_t)t.x << 15);
    g_edges[p1] = (uint32_t)s.y | ((uint32_t)t.y << 15);
    g_edges[p2] = (uint32_t)s.z | ((uint32_t)t.z << 15);
    g_edges[p3] = (uint32_t)s.w | ((uint32_t)t.w << 15);
}

// ---------------------------------------------------------------------------
// Prep B2 (virtual K = 3840): k<3072: blk=k>>10 -> basis[b][i][n], blk<2 hi else lo
// k>=3072: loop part, blk=(k-3072)>>8 -> loop_w[i][n], blk<2 hi else lo
// ---------------------------------------------------------------------------
__global__ void __launch_bounds__(256) prep_b2_kernel(const float* __restrict__ basis,
                                                      const float* __restrict__ loopw) {
    int n = blockIdx.x;   // 0..255
    for (int k = threadIdx.x; k < KTOT; k += 256) {
        float w; int blk;
        if (k < 3072) {
            blk = k >> 10;
            int kk = k & 1023;
            int b = kk >> 8, i = kk & 255;
            w = basis[(size_t)b * 65536 + (size_t)i * 256 + n];
        } else {
            int kk = k - 3072;
            blk = kk >> 8;
            int i = kk & 255;
            w = loopw[(size_t)i * 256 + n];
        }
        __nv_bfloat16 hi = __float2bfloat16(w);
        __nv_bfloat16 out = (blk < 2) ? hi : __float2bfloat16(w - __bfloat162float(hi));
        g_B2[(size_t)n * KTOT + k] = out;
    }
}

// ---------------------------------------------------------------------------
// Fused gather + aggregate + combine + split: one warp per node.
// A row layout (KA=2560): [T_hi(1024)|T_lo(1024)|x_hi(256)|x_lo(256)]
// ---------------------------------------------------------------------------
__device__ __forceinline__ void split8_store2(__nv_bfloat16* rowbase, int off_hi, int off_lo,
                                              const float* v) {
    union { __nv_bfloat162 h2[4]; uint4 u; } phi, plo;
#pragma unroll
    for (int q = 0; q < 4; q++) {
        float a = v[q * 2], b = v[q * 2 + 1];
        __nv_bfloat16 ha = __float2bfloat16(a), hb = __float2bfloat16(b);
        __nv_bfloat16 la = __float2bfloat16(a - __bfloat162float(ha));
        __nv_bfloat16 lb = __float2bfloat16(b - __bfloat162float(hb));
        phi.h2[q] = __nv_bfloat162(ha, hb);
        plo.h2[q] = __nv_bfloat162(la, lb);
    }
    *(uint4*)(rowbase + off_hi) = phi.u;
    *(uint4*)(rowbase + off_lo) = plo.u;
}

__global__ void __launch_bounds__(256) agg_kernel(const float* __restrict__ x,
                                                  const float* __restrict__ comp) {
    __shared__ float4 cs4[N_RELS];
    int tid = threadIdx.x;
    if (tid < N_RELS)
        cs4[tid] = make_float4(comp[tid * 4 + 0], comp[tid * 4 + 1], comp[tid * 4 + 2], comp[tid * 4 + 3]);
    __syncthreads();

    int v = blockIdx.x * 8 + (tid >> 5);
    int lane = tid & 31;
    if (v >= N_NODES) return;

    int s0 = g_start[v];
    int s1 = g_start[v + 1];
    int c0 = lane * 8;

    float accT[4][8];
#pragma unroll
    for (int b = 0; b < 4; b++)
#pragma unroll
        for (int j = 0; j < 8; j++) accT[b][j] = 0.f;

    auto accum = [&](uint32_t p, float4 xa, float4 xb) {
        float4 cv = cs4[p >> 15];
        float c;
        c = cv.x;
        accT[0][0] += c * xa.x; accT[0][1] += c * xa.y; accT[0][2] += c * xa.z; accT[0][3] += c * xa.w;
        accT[0][4] += c * xb.x; accT[0][5] += c * xb.y; accT[0][6] += c * xb.z; accT[0][7] += c * xb.w;
        c = cv.y;
        accT[1][0] += c * xa.x; accT[1][1] += c * xa.y; accT[1][2] += c * xa.z; accT[1][3] += c * xa.w;
        accT[1][4] += c * xb.x; accT[1][5] += c * xb.y; accT[1][6] += c * xb.z; accT[1][7] += c * xb.w;
        c = cv.z;
        accT[2][0] += c * xa.x; accT[2][1] += c * xa.y; accT[2][2] += c * xa.z; accT[2][3] += c * xa.w;
        accT[2][4] += c * xb.x; accT[2][5] += c * xb.y; accT[2][6] += c * xb.z; accT[2][7] += c * xb.w;
        c = cv.w;
        accT[3][0] += c * xa.x; accT[3][1] += c * xa.y; accT[3][2] += c * xa.z; accT[3][3] += c * xa.w;
        accT[3][4] += c * xb.x; accT[3][5] += c * xb.y; accT[3][6] += c * xb.z; accT[3][7] += c * xb.w;
    };

    int e = s0;
    for (; e + 4 <= s1; e += 4) {
        uint32_t p[4];
        float4 xa[4], xb[4];
#pragma unroll
        for (int j = 0; j < 4; j++) p[j] = __ldg(&g_edges[e + j]);
#pragma unroll
        for (int j = 0; j < 4; j++) {
            const float4* xr = (const float4*)(x + (size_t)(p[j] & 32767) * 256 + c0);
            xa[j] = __ldg(xr);
            xb[j] = __ldg(xr + 1);
        }
#pragma unroll
        for (int j = 0; j < 4; j++) accum(p[j], xa[j], xb[j]);
    }
    for (; e < s1; e++) {
        uint32_t p = __ldg(&g_edges[e]);
        const float4* xr = (const float4*)(x + (size_t)(p & 32767) * 256 + c0);
        accum(p, __ldg(xr), __ldg(xr + 1));
    }

    __nv_bfloat16* arow = g_A3 + (size_t)v * KA;
#pragma unroll
    for (int b = 0; b < 4; b++) {
        int o = b * 256 + c0;
        split8_store2(arow, o, 1024 + o, accT[b]);
    }
    {
        const float4* xr = (const float4*)(x + (size_t)v * 256 + c0);
        float4 xa = __ldg(xr), xb = __ldg(xr + 1);
        float xv[8] = { xa.x, xa.y, xa.z, xa.w, xb.x, xb.y, xb.z, xb.w };
        split8_store2(arow, 2048 + c0, 2304 + c0, xv);
    }
}

// ---------------------------------------------------------------------------
// GEMM: agg[20000,256] += A[seg-mapped K] @ B2seg^T.  Virtual K = 3840, 3 segs.
// Virtual->physical A k-map (chunk-constant, boundaries 256-aligned):
//   kv<2048: kv | kv<3072: kv-2048 | kv<3584: kv-1024 | else kv-1536
// Tile M=64, N=256, K-chunk 32, double-buffered cp.async, 256 threads.
// ---------------------------------------------------------------------------
#define KCH 32
#define NCH (KSEG / KCH)        // 40
#define ROWB 80
#define A_TILE (64 * ROWB)      // 5120
#define B_TILE (256 * ROWB)     // 20480
#define GEMM_SMEM (2 * A_TILE + 2 * B_TILE)   // 51200

__device__ __forceinline__ int amap(int kv) {
    return (kv < 2048) ? kv : ((kv < 3072) ? kv - 2048 : ((kv < 3584) ? kv - 1024 : kv - 1536));
}

__global__ void __launch_bounds__(256) gemm_mma_kernel() {
    extern __shared__ __align__(16) char dyn[];
    const uint32_t sAu[2] = { smem_to_u32(dyn), smem_to_u32(dyn + A_TILE) };
    const uint32_t sBu[2] = { smem_to_u32(dyn + 2 * A_TILE), smem_to_u32(dyn + 2 * A_TILE + B_TILE) };

    const int tid = threadIdx.x;
    const int lane = tid & 31;
    const int wid = tid >> 5;
    const int warp_m = wid & 1;
    const int warp_n = wid >> 1;
    const int seg = blockIdx.x;
    const int m0 = blockIdx.y * 64;
    const int kseg = seg * KSEG;

    const int ar = tid >> 2;
    const int ac = tid & 3;
    const int am = m0 + ar;
    const int asz = (am < N_NODES) ? 16 : 0;
    const __nv_bfloat16* aBase = g_A3 + (size_t)((am < N_NODES) ? am : 0) * KA + ac * 8;
    const uint32_t aDst = ar * ROWB + ac * 16;

    auto load_chunk = [&](int c, int s) {
        int kv = kseg + c * KCH;
        int ka = amap(kv);
        cp_async16(sAu[s] + aDst, aBase + ka, asz);
#pragma unroll
        for (int i = 0; i < 4; i++) {
            int cid = tid + i * 256;
            int br = cid >> 2, bc = cid & 3;
            cp_async16(sBu[s] + br * ROWB + bc * 16,
                       g_B2 + (size_t)br * KTOT + kv + bc * 8, 16);
        }
        cp_async_commit();
    };

    float acc[2][8][4];
#pragma unroll
    for (int i = 0; i < 2; i++)
#pragma unroll
        for (int t = 0; t < 8; t++)
#pragma unroll
            for (int q = 0; q < 4; q++) acc[i][t][q] = 0.0f;

    const uint32_t aLd = (warp_m * 32 + (lane & 15)) * ROWB + (lane >> 4) * 16;
    const uint32_t bLd = (warp_n * 64 + ((lane >> 4) << 3) + (lane & 7)) * ROWB + (((lane >> 3) & 1) << 4);

    load_chunk(0, 0);
    for (int c = 0; c < NCH; c++) {
        if (c + 1 < NCH) load_chunk(c + 1, (c + 1) & 1);
        if (c + 1 < NCH) cp_async_wait<1>(); else cp_async_wait<0>();
        __syncthreads();
        const int s = c & 1;
#pragma unroll
        for (int kk = 0; kk < 2; kk++) {
            uint32_t a[2][4];
#pragma unroll
            for (int i = 0; i < 2; i++)
                ldsm_x4(a[i][0], a[i][1], a[i][2], a[i][3],
                        sAu[s] + aLd + i * 16 * ROWB + kk * 32);
            uint32_t b[4][4];
#pragma unroll
            for (int j = 0; j < 4; j++)
                ldsm_x4(b[j][0], b[j][1], b[j][2], b[j][3],
                        sBu[s] + bLd + j * 16 * ROWB + kk * 32);
#pragma unroll
            for (int i = 0; i < 2; i++)
#pragma unroll
                for (int t = 0; t < 8; t++)
                    mma16816(acc[i][t], a[i][0], a[i][1], a[i][2], a[i][3],
                             b[t >> 1][(t & 1) * 2], b[t >> 1][(t & 1) * 2 + 1]);
        }
        __syncthreads();
    }

    const int colBase = warp_n * 64 + (lane & 3) * 2;
#pragma unroll
    for (int i = 0; i < 2; i++) {
        int r0 = m0 + warp_m * 32 + i * 16 + (lane >> 2);
#pragma unroll
        for (int half = 0; half < 2; half++) {
            int r = r0 + half * 8;
            if (r < N_NODES) {
                float* arow = g_agg + (size_t)r * 256;
#pragma unroll
                for (int t = 0; t < 8; t++)
                    red_add_v2(arow + colBase + t * 8, acc[i][t][half * 2], acc[i][t][half * 2 + 1]);
            }
        }
    }
}

// ---------------------------------------------------------------------------
// Epilogue: h = gelu(agg + bias + x); out = LN(h)*gamma + beta
// ---------------------------------------------------------------------------
__global__ void __launch_bounds__(256) epilogue_kernel(const float* __restrict__ x,
                                                       const float* __restrict__ bias,
                                                       const float* __restrict__ gamma,
                                                       const float* __restrict__ beta,
                                                       float* __restrict__ out) {
    int gid = blockIdx.x * blockDim.x + threadIdx.x;
    int n = gid >> 5;
    int lane = gid & 31;
    if (n >= N_NODES) return;

    const float4* arow = (const float4*)(g_agg + (size_t)n * 256);
    const float4* xrow = (const float4*)(x + (size_t)n * 256);
    float4 t0 = arow[lane], t1 = arow[lane + 32];
    float4 x0 = xrow[lane], x1 = xrow[lane + 32];
    float4 bb0 = ((const float4*)bias)[lane];
    float4 bb1 = ((const float4*)bias)[lane + 32];

    float h[8];
    h[0] = gelu_exact(t0.x + bb0.x + x0.x);
    h[1] = gelu_exact(t0.y + bb0.y + x0.y);
    h[2] = gelu_exact(t0.z + bb0.z + x0.z);
    h[3] = gelu_exact(t0.w + bb0.w + x0.w);
    h[4] = gelu_exact(t1.x + bb1.x + x1.x);
    h[5] = gelu_exact(t1.y + bb1.y + x1.y);
    h[6] = gelu_exact(t1.z + bb1.z + x1.z);
    h[7] = gelu_exact(t1.w + bb1.w + x1.w);

    float s = 0.f;
#pragma unroll
    for (int i = 0; i < 8; i++) s += h[i];
#pragma unroll
    for (int off = 16; off > 0; off >>= 1) s += __shfl_xor_sync(0xffffffffu, s, off);
    float mu = s * (1.0f / 256.0f);

    float v = 0.f;
#pragma unroll
    for (int i = 0; i < 8; i++) {
        float dlt = h[i] - mu;
        v = fmaf(dlt, dlt, v);
    }
#pragma unroll
    for (int off = 16; off > 0; off >>= 1) v += __shfl_xor_sync(0xffffffffu, v, off);
    float inv = rsqrtf(v * (1.0f / 256.0f) + 1e-5f);

    float4 g0 = ((const float4*)gamma)[lane];
    float4 g1 = ((const float4*)gamma)[lane + 32];
    float4 b0 = ((const float4*)beta)[lane];
    float4 b1 = ((const float4*)beta)[lane + 32];

    float4 o0, o1;
    o0.x = (h[0] - mu) * inv * g0.x + b0.x;
    o0.y = (h[1] - mu) * inv * g0.y + b0.y;
    o0.z = (h[2] - mu) * inv * g0.z + b0.z;
    o0.w = (h[3] - mu) * inv * g0.w + b0.w;
    o1.x = (h[4] - mu) * inv * g1.x + b1.x;
    o1.y = (h[5] - mu) * inv * g1.y + b1.y;
    o1.z = (h[6] - mu) * inv * g1.z + b1.z;
    o1.w = (h[7] - mu) * inv * g1.w + b1.w;

    float4* orow = (float4*)(out + (size_t)n * 256);
    orow[lane] = o0;
    orow[lane + 32] = o1;
}

extern "C" void kernel_launch(void* const* d_in, const int* in_sizes, int n_in,
                              void* d_out, int out_size) {
    const float* x     = (const float*)d_in[0];
    const int*   src   = (const int*)  d_in[1];
    const int*   dst   = (const int*)  d_in[2];
    const int*   et    = (const int*)  d_in[3];
    const float* basis = (const float*)d_in[4];
    const float* comp  = (const float*)d_in[5];
    const float* loopw = (const float*)d_in[6];
    const float* bias  = (const float*)d_in[7];
    const float* gamma = (const float*)d_in[8];
    const float* beta  = (const float*)d_in[9];
    float* out = (float*)d_out;

    static bool attr_set = false;
    if (!attr_set) {
        cudaFuncSetAttribute(gemm_mma_kernel, cudaFuncAttributeMaxDynamicSharedMemorySize, GEMM_SMEM);
        attr_set = true;
    }

    zero_kernel<<<(N_NODES * 64 + 255) / 256, 256>>>();
    hist_kernel<<<(N_EDGES / 4 + 255) / 256, 256>>>(dst);
    scan_kernel<<<1, 1024>>>();
    reorder_kernel<<<(N_EDGES / 4 + 255) / 256, 256>>>(src, dst, et);
    prep_b2_kernel<<<256, 256>>>(basis, loopw);
    agg_kernel<<<(N_NODES + 7) / 8, 256>>>(x, comp);
    dim3 gg(3, (N_NODES + 63) / 64);
    gemm_mma_kernel<<<gg, 256, GEMM_SMEM>>>();
    epilogue_kernel<<<(N_NODES * 32 + 255) / 256, 256>>>(x, bias, gamma, beta, out);
}

// round 10
// speedup vs baseline: 1.1104x; 1.1104x over previous
#include <cuda_runtime.h>
#include <cuda_fp16.h>
#include <math.h>
#include <cstdint>

#define N_NODES 20000
#define N_EDGES 640000
#define D 256
#define N_RELS 8
#define N_BASES 4
#define KA 2560              // A & B K: [T_hi(1024)|T_lo(1024)|x_hi(256)|x_lo(256)] fp16

// ---------------- device scratch (allocation-free rule) ----------------
__device__ __align__(16) __half g_A3[(size_t)N_NODES * KA];    // 102MB fp16
__device__ __align__(16) __half g_B2[(size_t)256 * KA];        // 1.3MB [out-col n][k]
__device__ float g_agg[(size_t)N_NODES * 256];                 // 20MB (written by GEMM)
__device__ int g_hist[N_NODES];
__device__ int g_cursor[N_NODES];
__device__ int g_start[N_NODES + 1];
__device__ uint32_t g_edges[N_EDGES];   // packed src | (type<<15)

__device__ __forceinline__ float gelu_exact(float x) {
    return 0.5f * x * (1.0f + erff(x * 0.70710678118654752440f));
}
__device__ __forceinline__ uint32_t smem_to_u32(const void* p) {
    uint32_t a;
    asm("{ .reg .u64 t; cvta.to.shared.u64 t, %1; cvt.u32.u64 %0, t; }" : "=r"(a) : "l"(p));
    return a;
}
__device__ __forceinline__ void cp_async16(uint32_t dst, const void* src, int src_sz) {
    asm volatile("cp.async.cg.shared.global [%0], [%1], 16, %2;" :: "r"(dst), "l"(src), "r"(src_sz) : "memory");
}
__device__ __forceinline__ void cp_async_commit() { asm volatile("cp.async.commit_group;" ::: "memory"); }
template <int N> __device__ __forceinline__ void cp_async_wait() {
    asm volatile("cp.async.wait_group %0;" :: "n"(N) : "memory");
}
__device__ __forceinline__ void ldsm_x4(uint32_t& r0, uint32_t& r1, uint32_t& r2, uint32_t& r3, uint32_t addr) {
    asm volatile("ldmatrix.sync.aligned.m8n8.x4.shared.b16 {%0,%1,%2,%3}, [%4];"
                 : "=r"(r0), "=r"(r1), "=r"(r2), "=r"(r3) : "r"(addr));
}
__device__ __forceinline__ void mma16816(float* d, uint32_t a0, uint32_t a1, uint32_t a2, uint32_t a3,
                                         uint32_t b0, uint32_t b1) {
    asm volatile("mma.sync.aligned.m16n8k16.row.col.f32.f16.f16.f32 "
                 "{%0,%1,%2,%3}, {%4,%5,%6,%7}, {%8,%9}, {%0,%1,%2,%3};"
                 : "+f"(d[0]), "+f"(d[1]), "+f"(d[2]), "+f"(d[3])
                 : "r"(a0), "r"(a1), "r"(a2), "r"(a3), "r"(b0), "r"(b1));
}

// ---------------------------------------------------------------------------
// Zero g_hist
// ---------------------------------------------------------------------------
__global__ void __launch_bounds__(256) zero_kernel() {
    int gid = blockIdx.x * blockDim.x + threadIdx.x;
    if (gid < N_NODES) g_hist[gid] = 0;
}

// 4 edges per thread (N_EDGES % 4 == 0)
__global__ void __launch_bounds__(256) hist_kernel(const int* __restrict__ dst) {
    int g4 = (blockIdx.x * blockDim.x + threadIdx.x) * 4;
    if (g4 >= N_EDGES) return;
    int4 d = *(const int4*)(dst + g4);
    atomicAdd(&g_hist[d.x], 1);
    atomicAdd(&g_hist[d.y], 1);
    atomicAdd(&g_hist[d.z], 1);
    atomicAdd(&g_hist[d.w], 1);
}

// single block 1024 threads, 20 bins each
__global__ void __launch_bounds__(1024) scan_kernel() {
    __shared__ int sm[1024];
    int t = threadIdx.x;
    int base = t * 20;
    int cnt[20];
    int s = 0;
#pragma unroll
    for (int i = 0; i < 20; i++) {
        int idx = base + i;
        int c = (idx < N_NODES) ? g_hist[idx] : 0;
        cnt[i] = c; s += c;
    }
    sm[t] = s;
    __syncthreads();
    for (int off = 1; off < 1024; off <<= 1) {
        int v = (t >= off) ? sm[t - off] : 0;
        __syncthreads();
        sm[t] += v;
        __syncthreads();
    }
    int run = (t > 0) ? sm[t - 1] : 0;
#pragma unroll
    for (int i = 0; i < 20; i++) {
        int idx = base + i;
        if (idx < N_NODES) {
            g_start[idx] = run;
            g_cursor[idx] = run;
            run += cnt[i];
        }
    }
    if (t == 1023) g_start[N_NODES] = sm[1023];
}

// 4 edges per thread
__global__ void __launch_bounds__(256) reorder_kernel(const int* __restrict__ src,
                                                      const int* __restrict__ dst,
                                                      const int* __restrict__ et) {
    int g4 = (blockIdx.x * blockDim.x + threadIdx.x) * 4;
    if (g4 >= N_EDGES) return;
    int4 s = *(const int4*)(src + g4);
    int4 d = *(const int4*)(dst + g4);
    int4 t = *(const int4*)(et + g4);
    int p0 = atomicAdd(&g_cursor[d.x], 1);
    int p1 = atomicAdd(&g_cursor[d.y], 1);
    int p2 = atomicAdd(&g_cursor[d.z], 1);
    int p3 = atomicAdd(&g_cursor[d.w], 1);
    g_edges[p0] = (uint32_t)s.x | ((uint32_t)t.x << 15);
    g_edges[p1] = (uint32_t)s.y | ((uint32_t)t.y << 15);
    g_edges[p2] = (uint32_t)s.z | ((uint32_t)t.z << 15);
    g_edges[p3] = (uint32_t)s.w | ((uint32_t)t.w << 15);
}

// ---------------------------------------------------------------------------
// Prep B2 (K = 2560 fp16):
//   k<2048  : b=(k&1023)>>8, i=k&255 -> fp16(basis[b][i][n])   (W_hi, used for T_hi and T_lo)
//   k>=2048 : i=k&255           -> fp16(loop_w[i][n])          (loop_hi, used for x_hi and x_lo)
// ---------------------------------------------------------------------------
__global__ void __launch_bounds__(256) prep_b2_kernel(const float* __restrict__ basis,
                                                      const float* __restrict__ loopw) {
    int n = blockIdx.x;   // 0..255
    for (int k = threadIdx.x; k < KA; k += 256) {
        float w;
        if (k < 2048) {
            int b = (k & 1023) >> 8, i = k & 255;
            w = basis[(size_t)b * 65536 + (size_t)i * 256 + n];
        } else {
            int i = k & 255;
            w = loopw[(size_t)i * 256 + n];
        }
        g_B2[(size_t)n * KA + k] = __float2half(w);
    }
}

// ---------------------------------------------------------------------------
// Fused gather + aggregate + combine + fp16 split: one warp per node.
// A row layout: [T_hi(1024)|T_lo(1024)|x_hi(256)|x_lo(256)]
// ---------------------------------------------------------------------------
__device__ __forceinline__ void split8_store2(__half* rowbase, int off_hi, int off_lo,
                                              const float* v) {
    union { __half2 h2[4]; uint4 u; } phi, plo;
#pragma unroll
    for (int q = 0; q < 4; q++) {
        float a = v[q * 2], b = v[q * 2 + 1];
        __half ha = __float2half(a), hb = __float2half(b);
        __half la = __float2half(a - __half2float(ha));
        __half lb = __float2half(b - __half2float(hb));
        phi.h2[q] = __halves2half2(ha, hb);
        plo.h2[q] = __halves2half2(la, lb);
    }
    *(uint4*)(rowbase + off_hi) = phi.u;
    *(uint4*)(rowbase + off_lo) = plo.u;
}

__global__ void __launch_bounds__(256) agg_kernel(const float* __restrict__ x,
                                                  const float* __restrict__ comp) {
    __shared__ float4 cs4[N_RELS];
    int tid = threadIdx.x;
    if (tid < N_RELS)
        cs4[tid] = make_float4(comp[tid * 4 + 0], comp[tid * 4 + 1], comp[tid * 4 + 2], comp[tid * 4 + 3]);
    __syncthreads();

    int v = blockIdx.x * 8 + (tid >> 5);
    int lane = tid & 31;
    if (v >= N_NODES) return;

    int s0 = g_start[v];
    int s1 = g_start[v + 1];
    int c0 = lane * 8;

    float accT[4][8];
#pragma unroll
    for (int b = 0; b < 4; b++)
#pragma unroll
        for (int j = 0; j < 8; j++) accT[b][j] = 0.f;

    auto accum = [&](uint32_t p, float4 xa, float4 xb) {
        float4 cv = cs4[p >> 15];
        float c;
        c = cv.x;
        accT[0][0] += c * xa.x; accT[0][1] += c * xa.y; accT[0][2] += c * xa.z; accT[0][3] += c * xa.w;
        accT[0][4] += c * xb.x; accT[0][5] += c * xb.y; accT[0][6] += c * xb.z; accT[0][7] += c * xb.w;
        c = cv.y;
        accT[1][0] += c * xa.x; accT[1][1] += c * xa.y; accT[1][2] += c * xa.z; accT[1][3] += c * xa.w;
        accT[1][4] += c * xb.x; accT[1][5] += c * xb.y; accT[1][6] += c * xb.z; accT[1][7] += c * xb.w;
        c = cv.z;
        accT[2][0] += c * xa.x; accT[2][1] += c * xa.y; accT[2][2] += c * xa.z; accT[2][3] += c * xa.w;
        accT[2][4] += c * xb.x; accT[2][5] += c * xb.y; accT[2][6] += c * xb.z; accT[2][7] += c * xb.w;
        c = cv.w;
        accT[3][0] += c * xa.x; accT[3][1] += c * xa.y; accT[3][2] += c * xa.z; accT[3][3] += c * xa.w;
        accT[3][4] += c * xb.x; accT[3][5] += c * xb.y; accT[3][6] += c * xb.z; accT[3][7] += c * xb.w;
    };

    int e = s0;
    for (; e + 4 <= s1; e += 4) {
        uint32_t p[4];
        float4 xa[4], xb[4];
#pragma unroll
        for (int j = 0; j < 4; j++) p[j] = __ldg(&g_edges[e + j]);
#pragma unroll
        for (int j = 0; j < 4; j++) {
            const float4* xr = (const float4*)(x + (size_t)(p[j] & 32767) * 256 + c0);
            xa[j] = __ldg(xr);
            xb[j] = __ldg(xr + 1);
        }
#pragma unroll
        for (int j = 0; j < 4; j++) accum(p[j], xa[j], xb[j]);
    }
    for (; e < s1; e++) {
        uint32_t p = __ldg(&g_edges[e]);
        const float4* xr = (const float4*)(x + (size_t)(p & 32767) * 256 + c0);
        accum(p, __ldg(xr), __ldg(xr + 1));
    }

    __half* arow = g_A3 + (size_t)v * KA;
#pragma unroll
    for (int b = 0; b < 4; b++) {
        int o = b * 256 + c0;
        split8_store2(arow, o, 1024 + o, accT[b]);
    }
    {
        const float4* xr = (const float4*)(x + (size_t)v * 256 + c0);
        float4 xa = __ldg(xr), xb = __ldg(xr + 1);
        float xv[8] = { xa.x, xa.y, xa.z, xa.w, xb.x, xb.y, xb.z, xb.w };
        split8_store2(arow, 2048 + c0, 2304 + c0, xv);
    }
}

// ---------------------------------------------------------------------------
// GEMM: agg[20000,256] = A[20000,2560] @ B2^T   (single K pass, plain stores)
// Tile M=64, N=256, K-chunk 32, double-buffered cp.async, 256 threads.
// grid = 313 m-tiles.
// ---------------------------------------------------------------------------
#define KCH 32
#define NCH (KA / KCH)          // 80
#define ROWB 80
#define A_TILE (64 * ROWB)      // 5120
#define B_TILE (256 * ROWB)     // 20480
#define GEMM_SMEM (2 * A_TILE + 2 * B_TILE)   // 51200

__global__ void __launch_bounds__(256) gemm_mma_kernel() {
    extern __shared__ __align__(16) char dyn[];
    const uint32_t sAu[2] = { smem_to_u32(dyn), smem_to_u32(dyn + A_TILE) };
    const uint32_t sBu[2] = { smem_to_u32(dyn + 2 * A_TILE), smem_to_u32(dyn + 2 * A_TILE + B_TILE) };

    const int tid = threadIdx.x;
    const int lane = tid & 31;
    const int wid = tid >> 5;
    const int warp_m = wid & 1;
    const int warp_n = wid >> 1;
    const int m0 = blockIdx.x * 64;

    const int ar = tid >> 2;
    const int ac = tid & 3;
    const int am = m0 + ar;
    const int asz = (am < N_NODES) ? 16 : 0;
    const __half* aBase = g_A3 + (size_t)((am < N_NODES) ? am : 0) * KA + ac * 8;
    const uint32_t aDst = ar * ROWB + ac * 16;

    auto load_chunk = [&](int c, int s) {
        int k0 = c * KCH;
        cp_async16(sAu[s] + aDst, aBase + k0, asz);
#pragma unroll
        for (int i = 0; i < 4; i++) {
            int cid = tid + i * 256;
            int br = cid >> 2, bc = cid & 3;
            cp_async16(sBu[s] + br * ROWB + bc * 16,
                       g_B2 + (size_t)br * KA + k0 + bc * 8, 16);
        }
        cp_async_commit();
    };

    float acc[2][8][4];
#pragma unroll
    for (int i = 0; i < 2; i++)
#pragma unroll
        for (int t = 0; t < 8; t++)
#pragma unroll
            for (int q = 0; q < 4; q++) acc[i][t][q] = 0.0f;

    const uint32_t aLd = (warp_m * 32 + (lane & 15)) * ROWB + (lane >> 4) * 16;
    const uint32_t bLd = (warp_n * 64 + ((lane >> 4) << 3) + (lane & 7)) * ROWB + (((lane >> 3) & 1) << 4);

    load_chunk(0, 0);
    for (int c = 0; c < NCH; c++) {
        if (c + 1 < NCH) load_chunk(c + 1, (c + 1) & 1);
        if (c + 1 < NCH) cp_async_wait<1>(); else cp_async_wait<0>();
        __syncthreads();
        const int s = c & 1;
#pragma unroll
        for (int kk = 0; kk < 2; kk++) {
            uint32_t a[2][4];
#pragma unroll
            for (int i = 0; i < 2; i++)
                ldsm_x4(a[i][0], a[i][1], a[i][2], a[i][3],
                        sAu[s] + aLd + i * 16 * ROWB + kk * 32);
            uint32_t b[4][4];
#pragma unroll
            for (int j = 0; j < 4; j++)
                ldsm_x4(b[j][0], b[j][1], b[j][2], b[j][3],
                        sBu[s] + bLd + j * 16 * ROWB + kk * 32);
#pragma unroll
            for (int i = 0; i < 2; i++)
#pragma unroll
                for (int t = 0; t < 8; t++)
                    mma16816(acc[i][t], a[i][0], a[i][1], a[i][2], a[i][3],
                             b[t >> 1][(t & 1) * 2], b[t >> 1][(t & 1) * 2 + 1]);
        }
        __syncthreads();
    }

    const int colBase = warp_n * 64 + (lane & 3) * 2;
#pragma unroll
    for (int i = 0; i < 2; i++) {
        int r0 = m0 + warp_m * 32 + i * 16 + (lane >> 2);
#pragma unroll
        for (int half = 0; half < 2; half++) {
            int r = r0 + half * 8;
            if (r < N_NODES) {
                float* arow = g_agg + (size_t)r * 256;
#pragma unroll
                for (int t = 0; t < 8; t++)
                    *(float2*)(arow + colBase + t * 8) =
                        make_float2(acc[i][t][half * 2], acc[i][t][half * 2 + 1]);
            }
        }
    }
}

// ---------------------------------------------------------------------------
// Epilogue: h = gelu(agg + bias + x); out = LN(h)*gamma + beta
// ---------------------------------------------------------------------------
__global__ void __launch_bounds__(256) epilogue_kernel(const float* __restrict__ x,
                                                       const float* __restrict__ bias,
                                                       const float* __restrict__ gamma,
                                                       const float* __restrict__ beta,
                                                       float* __restrict__ out) {
    int gid = blockIdx.x * blockDim.x + threadIdx.x;
    int n = gid >> 5;
    int lane = gid & 31;
    if (n >= N_NODES) return;

    const float4* arow = (const float4*)(g_agg + (size_t)n * 256);
    const float4* xrow = (const float4*)(x + (size_t)n * 256);
    float4 t0 = arow[lane], t1 = arow[lane + 32];
    float4 x0 = xrow[lane], x1 = xrow[lane + 32];
    float4 bb0 = ((const float4*)bias)[lane];
    float4 bb1 = ((const float4*)bias)[lane + 32];

    float h[8];
    h[0] = gelu_exact(t0.x + bb0.x + x0.x);
    h[1] = gelu_exact(t0.y + bb0.y + x0.y);
    h[2] = gelu_exact(t0.z + bb0.z + x0.z);
    h[3] = gelu_exact(t0.w + bb0.w + x0.w);
    h[4] = gelu_exact(t1.x + bb1.x + x1.x);
    h[5] = gelu_exact(t1.y + bb1.y + x1.y);
    h[6] = gelu_exact(t1.z + bb1.z + x1.z);
    h[7] = gelu_exact(t1.w + bb1.w + x1.w);

    float s = 0.f;
#pragma unroll
    for (int i = 0; i < 8; i++) s += h[i];
#pragma unroll
    for (int off = 16; off > 0; off >>= 1) s += __shfl_xor_sync(0xffffffffu, s, off);
    float mu = s * (1.0f / 256.0f);

    float v = 0.f;
#pragma unroll
    for (int i = 0; i < 8; i++) {
        float dlt = h[i] - mu;
        v = fmaf(dlt, dlt, v);
    }
#pragma unroll
    for (int off = 16; off > 0; off >>= 1) v += __shfl_xor_sync(0xffffffffu, v, off);
    float inv = rsqrtf(v * (1.0f / 256.0f) + 1e-5f);

    float4 g0 = ((const float4*)gamma)[lane];
    float4 g1 = ((const float4*)gamma)[lane + 32];
    float4 b0 = ((const float4*)beta)[lane];
    float4 b1 = ((const float4*)beta)[lane + 32];

    float4 o0, o1;
    o0.x = (h[0] - mu) * inv * g0.x + b0.x;
    o0.y = (h[1] - mu) * inv * g0.y + b0.y;
    o0.z = (h[2] - mu) * inv * g0.z + b0.z;
    o0.w = (h[3] - mu) * inv * g0.w + b0.w;
    o1.x = (h[4] - mu) * inv * g1.x + b1.x;
    o1.y = (h[5] - mu) * inv * g1.y + b1.y;
    o1.z = (h[6] - mu) * inv * g1.z + b1.z;
    o1.w = (h[7] - mu) * inv * g1.w + b1.w;

    float4* orow = (float4*)(out + (size_t)n * 256);
    orow[lane] = o0;
    orow[lane + 32] = o1;
}

extern "C" void kernel_launch(void* const* d_in, const int* in_sizes, int n_in,
                              void* d_out, int out_size) {
    const float* x     = (const float*)d_in[0];
    const int*   src   = (const int*)  d_in[1];
    const int*   dst   = (const int*)  d_in[2];
    const int*   et    = (const int*)  d_in[3];
    const float* basis = (const float*)d_in[4];
    const float* comp  = (const float*)d_in[5];
    const float* loopw = (const float*)d_in[6];
    const float* bias  = (const float*)d_in[7];
    const float* gamma = (const float*)d_in[8];
    const float* beta  = (const float*)d_in[9];
    float* out = (float*)d_out;

    static bool attr_set = false;
    if (!attr_set) {
        cudaFuncSetAttribute(gemm_mma_kernel, cudaFuncAttributeMaxDynamicSharedMemorySize, GEMM_SMEM);
        attr_set = true;
    }

    zero_kernel<<<(N_NODES + 255) / 256, 256>>>();
    hist_kernel<<<(N_EDGES / 4 + 255) / 256, 256>>>(dst);
    scan_kernel<<<1, 1024>>>();
    reorder_kernel<<<(N_EDGES / 4 + 255) / 256, 256>>>(src, dst, et);
    prep_b2_kernel<<<256, 256>>>(basis, loopw);
    agg_kernel<<<(N_NODES + 7) / 8, 256>>>(x, comp);
    gemm_mma_kernel<<<(N_NODES + 63) / 64, 256, GEMM_SMEM>>>();
    epilogue_kernel<<<(N_NODES * 32 + 255) / 256, 256>>>(x, bias, gamma, beta, out);
}

// round 12
// speedup vs baseline: 1.5032x; 1.3537x over previous
#include <cuda_runtime.h>
#include <cuda_fp16.h>
#include <math.h>
#include <cstdint>

#define N_NODES 20000
#define N_EDGES 640000
#define D 256
#define N_RELS 8
#define N_BASES 4
#define KA 1280              // A & B K: [T_hi(1024)|x_hi(256)]  plain fp16

// ---------------- device scratch (allocation-free rule) ----------------
__device__ __align__(16) __half g_A3[(size_t)N_NODES * KA];    // 51MB fp16
__device__ __align__(16) __half g_B2[(size_t)256 * KA];        // 0.65MB [out-col n][k]
__device__ float g_agg[(size_t)N_NODES * 256];                 // 20MB (written by GEMM)
__device__ int g_hist[N_NODES];
__device__ int g_cursor[N_NODES];
__device__ int g_start[N_NODES + 1];
__device__ uint32_t g_edges[N_EDGES];   // packed src | (type<<15)

__device__ __forceinline__ float gelu_exact(float x) {
    return 0.5f * x * (1.0f + erff(x * 0.70710678118654752440f));
}
__device__ __forceinline__ uint32_t smem_to_u32(const void* p) {
    uint32_t a;
    asm("{ .reg .u64 t; cvta.to.shared.u64 t, %1; cvt.u32.u64 %0, t; }" : "=r"(a) : "l"(p));
    return a;
}
__device__ __forceinline__ void cp_async16(uint32_t dst, const void* src, int src_sz) {
    asm volatile("cp.async.cg.shared.global [%0], [%1], 16, %2;" :: "r"(dst), "l"(src), "r"(src_sz) : "memory");
}
__device__ __forceinline__ void cp_async_commit() { asm volatile("cp.async.commit_group;" ::: "memory"); }
template <int N> __device__ __forceinline__ void cp_async_wait() {
    asm volatile("cp.async.wait_group %0;" :: "n"(N) : "memory");
}
__device__ __forceinline__ void ldsm_x4(uint32_t& r0, uint32_t& r1, uint32_t& r2, uint32_t& r3, uint32_t addr) {
    asm volatile("ldmatrix.sync.aligned.m8n8.x4.shared.b16 {%0,%1,%2,%3}, [%4];"
                 : "=r"(r0), "=r"(r1), "=r"(r2), "=r"(r3) : "r"(addr));
}
__device__ __forceinline__ void mma16816(float* d, uint32_t a0, uint32_t a1, uint32_t a2, uint32_t a3,
                                         uint32_t b0, uint32_t b1) {
    asm volatile("mma.sync.aligned.m16n8k16.row.col.f32.f16.f16.f32 "
                 "{%0,%1,%2,%3}, {%4,%5,%6,%7}, {%8,%9}, {%0,%1,%2,%3};"
                 : "+f"(d[0]), "+f"(d[1]), "+f"(d[2]), "+f"(d[3])
                 : "r"(a0), "r"(a1), "r"(a2), "r"(a3), "r"(b0), "r"(b1));
}

// ---------------------------------------------------------------------------
// Zero g_hist
// ---------------------------------------------------------------------------
__global__ void __launch_bounds__(256) zero_kernel() {
    int gid = blockIdx.x * blockDim.x + threadIdx.x;
    if (gid < N_NODES) g_hist[gid] = 0;
}

// 8 edges per thread (N_EDGES % 8 == 0) — MLP for L2 atomic latency
__global__ void __launch_bounds__(256) hist_kernel(const int* __restrict__ dst) {
    int g8 = (blockIdx.x * blockDim.x + threadIdx.x) * 8;
    if (g8 >= N_EDGES) return;
    int4 d0 = *(const int4*)(dst + g8);
    int4 d1 = *(const int4*)(dst + g8 + 4);
    atomicAdd(&g_hist[d0.x], 1);
    atomicAdd(&g_hist[d0.y], 1);
    atomicAdd(&g_hist[d0.z], 1);
    atomicAdd(&g_hist[d0.w], 1);
    atomicAdd(&g_hist[d1.x], 1);
    atomicAdd(&g_hist[d1.y], 1);
    atomicAdd(&g_hist[d1.z], 1);
    atomicAdd(&g_hist[d1.w], 1);
}

// single block 1024 threads, 20 bins each
__global__ void __launch_bounds__(1024) scan_kernel() {
    __shared__ int sm[1024];
    int t = threadIdx.x;
    int base = t * 20;
    int cnt[20];
    int s = 0;
#pragma unroll
    for (int i = 0; i < 20; i++) {
        int idx = base + i;
        int c = (idx < N_NODES) ? g_hist[idx] : 0;
        cnt[i] = c; s += c;
    }
    sm[t] = s;
    __syncthreads();
    for (int off = 1; off < 1024; off <<= 1) {
        int v = (t >= off) ? sm[t - off] : 0;
        __syncthreads();
        sm[t] += v;
        __syncthreads();
    }
    int run = (t > 0) ? sm[t - 1] : 0;
#pragma unroll
    for (int i = 0; i < 20; i++) {
        int idx = base + i;
        if (idx < N_NODES) {
            g_start[idx] = run;
            g_cursor[idx] = run;
            run += cnt[i];
        }
    }
    if (t == 1023) g_start[N_NODES] = sm[1023];
}

// 8 edges per thread
__global__ void __launch_bounds__(256) reorder_kernel(const int* __restrict__ src,
                                                      const int* __restrict__ dst,
                                                      const int* __restrict__ et) {
    int g8 = (blockIdx.x * blockDim.x + threadIdx.x) * 8;
    if (g8 >= N_EDGES) return;
    int4 s0 = *(const int4*)(src + g8);
    int4 s1 = *(const int4*)(src + g8 + 4);
    int4 d0 = *(const int4*)(dst + g8);
    int4 d1 = *(const int4*)(dst + g8 + 4);
    int4 t0 = *(const int4*)(et + g8);
    int4 t1 = *(const int4*)(et + g8 + 4);
    int p0 = atomicAdd(&g_cursor[d0.x], 1);
    int p1 = atomicAdd(&g_cursor[d0.y], 1);
    int p2 = atomicAdd(&g_cursor[d0.z], 1);
    int p3 = atomicAdd(&g_cursor[d0.w], 1);
    int p4 = atomicAdd(&g_cursor[d1.x], 1);
    int p5 = atomicAdd(&g_cursor[d1.y], 1);
    int p6 = atomicAdd(&g_cursor[d1.z], 1);
    int p7 = atomicAdd(&g_cursor[d1.w], 1);
    g_edges[p0] = (uint32_t)s0.x | ((uint32_t)t0.x << 15);
    g_edges[p1] = (uint32_t)s0.y | ((uint32_t)t0.y << 15);
    g_edges[p2] = (uint32_t)s0.z | ((uint32_t)t0.z << 15);
    g_edges[p3] = (uint32_t)s0.w | ((uint32_t)t0.w << 15);
    g_edges[p4] = (uint32_t)s1.x | ((uint32_t)t1.x << 15);
    g_edges[p5] = (uint32_t)s1.y | ((uint32_t)t1.y << 15);
    g_edges[p6] = (uint32_t)s1.z | ((uint32_t)t1.z << 15);
    g_edges[p7] = (uint32_t)s1.w | ((uint32_t)t1.w << 15);
}

// ---------------------------------------------------------------------------
// Prep B2 (K = 1280 fp16):
//   k<1024  : b=k>>8, i=k&255 -> fp16(basis[b][i][n])
//   k>=1024 : i=k&255         -> fp16(loop_w[i][n])
// ---------------------------------------------------------------------------
__global__ void __launch_bounds__(256) prep_b2_kernel(const float* __restrict__ basis,
                                                      const float* __restrict__ loopw) {
    int n = blockIdx.x;   // 0..255
    for (int k = threadIdx.x; k < KA; k += 256) {
        float w;
        if (k < 1024) {
            int b = k >> 8, i = k & 255;
            w = basis[(size_t)b * 65536 + (size_t)i * 256 + n];
        } else {
            int i = k & 255;
            w = loopw[(size_t)i * 256 + n];
        }
        g_B2[(size_t)n * KA + k] = __float2half(w);
    }
}

// ---------------------------------------------------------------------------
// Fused gather + aggregate + combine + fp16 round: one warp per node.
// A row layout (KA=1280): [T_hi(1024)|x_hi(256)]
// ---------------------------------------------------------------------------
__device__ __forceinline__ void round8_store(__half* rowbase, int off, const float* v) {
    union { __half2 h2[4]; uint4 u; } p;
#pragma unroll
    for (int q = 0; q < 4; q++)
        p.h2[q] = __halves2half2(__float2half(v[q * 2]), __float2half(v[q * 2 + 1]));
    *(uint4*)(rowbase + off) = p.u;
}

__global__ void __launch_bounds__(256) agg_kernel(const float* __restrict__ x,
                                                  const float* __restrict__ comp) {
    __shared__ float4 cs4[N_RELS];
    int tid = threadIdx.x;
    if (tid < N_RELS)
        cs4[tid] = make_float4(comp[tid * 4 + 0], comp[tid * 4 + 1], comp[tid * 4 + 2], comp[tid * 4 + 3]);
    __syncthreads();

    int v = blockIdx.x * 8 + (tid >> 5);
    int lane = tid & 31;
    if (v >= N_NODES) return;

    int s0 = g_start[v];
    int s1 = g_start[v + 1];
    int c0 = lane * 8;

    float accT[4][8];
#pragma unroll
    for (int b = 0; b < 4; b++)
#pragma unroll
        for (int j = 0; j < 8; j++) accT[b][j] = 0.f;

    auto accum = [&](uint32_t p, float4 xa, float4 xb) {
        float4 cv = cs4[p >> 15];
        float c;
        c = cv.x;
        accT[0][0] += c * xa.x; accT[0][1] += c * xa.y; accT[0][2] += c * xa.z; accT[0][3] += c * xa.w;
        accT[0][4] += c * xb.x; accT[0][5] += c * xb.y; accT[0][6] += c * xb.z; accT[0][7] += c * xb.w;
        c = cv.y;
        accT[1][0] += c * xa.x; accT[1][1] += c * xa.y; accT[1][2] += c * xa.z; accT[1][3] += c * xa.w;
        accT[1][4] += c * xb.x; accT[1][5] += c * xb.y; accT[1][6] += c * xb.z; accT[1][7] += c * xb.w;
        c = cv.z;
        accT[2][0] += c * xa.x; accT[2][1] += c * xa.y; accT[2][2] += c * xa.z; accT[2][3] += c * xa.w;
        accT[2][4] += c * xb.x; accT[2][5] += c * xb.y; accT[2][6] += c * xb.z; accT[2][7] += c * xb.w;
        c = cv.w;
        accT[3][0] += c * xa.x; accT[3][1] += c * xa.y; accT[3][2] += c * xa.z; accT[3][3] += c * xa.w;
        accT[3][4] += c * xb.x; accT[3][5] += c * xb.y; accT[3][6] += c * xb.z; accT[3][7] += c * xb.w;
    };

    int e = s0;
    for (; e + 4 <= s1; e += 4) {
        uint32_t p[4];
        float4 xa[4], xb[4];
#pragma unroll
        for (int j = 0; j < 4; j++) p[j] = __ldg(&g_edges[e + j]);
#pragma unroll
        for (int j = 0; j < 4; j++) {
            const float4* xr = (const float4*)(x + (size_t)(p[j] & 32767) * 256 + c0);
            xa[j] = __ldg(xr);
            xb[j] = __ldg(xr + 1);
        }
#pragma unroll
        for (int j = 0; j < 4; j++) accum(p[j], xa[j], xb[j]);
    }
    for (; e < s1; e++) {
        uint32_t p = __ldg(&g_edges[e]);
        const float4* xr = (const float4*)(x + (size_t)(p & 32767) * 256 + c0);
        accum(p, __ldg(xr), __ldg(xr + 1));
    }

    __half* arow = g_A3 + (size_t)v * KA;
#pragma unroll
    for (int b = 0; b < 4; b++)
        round8_store(arow, b * 256 + c0, accT[b]);
    {
        const float4* xr = (const float4*)(x + (size_t)v * 256 + c0);
        float4 xa = __ldg(xr), xb = __ldg(xr + 1);
        float xv[8] = { xa.x, xa.y, xa.z, xa.w, xb.x, xb.y, xb.z, xb.w };
        round8_store(arow, 1024 + c0, xv);
    }
}

// ---------------------------------------------------------------------------
// GEMM: agg[20000,256] = A[20000,1280] @ B2^T   (single K pass, plain stores)
// Tile M=64, N=256, K-chunk 32, double-buffered cp.async, 256 threads.
// grid = 313 m-tiles.
// ---------------------------------------------------------------------------
#define KCH 32
#define NCH (KA / KCH)          // 40
#define ROWB 80
#define A_TILE (64 * ROWB)      // 5120
#define B_TILE (256 * ROWB)     // 20480
#define GEMM_SMEM (2 * A_TILE + 2 * B_TILE)   // 51200

__global__ void __launch_bounds__(256) gemm_mma_kernel() {
    extern __shared__ __align__(16) char dyn[];
    const uint32_t sAu[2] = { smem_to_u32(dyn), smem_to_u32(dyn + A_TILE) };
    const uint32_t sBu[2] = { smem_to_u32(dyn + 2 * A_TILE), smem_to_u32(dyn + 2 * A_TILE + B_TILE) };

    const int tid = threadIdx.x;
    const int lane = tid & 31;
    const int wid = tid >> 5;
    const int warp_m = wid & 1;
    const int warp_n = wid >> 1;
    const int m0 = blockIdx.x * 64;

    const int ar = tid >> 2;
    const int ac = tid & 3;
    const int am = m0 + ar;
    const int asz = (am < N_NODES) ? 16 : 0;
    const __half* aBase = g_A3 + (size_t)((am < N_NODES) ? am : 0) * KA + ac * 8;
    const uint32_t aDst = ar * ROWB + ac * 16;

    auto load_chunk = [&](int c, int s) {
        int k0 = c * KCH;
        cp_async16(sAu[s] + aDst, aBase + k0, asz);
#pragma unroll
        for (int i = 0; i < 4; i++) {
            int cid = tid + i * 256;
            int br = cid >> 2, bc = cid & 3;
            cp_async16(sBu[s] + br * ROWB + bc * 16,
                       g_B2 + (size_t)br * KA + k0 + bc * 8, 16);
        }
        cp_async_commit();
    };

    float acc[2][8][4];
#pragma unroll
    for (int i = 0; i < 2; i++)
#pragma unroll
        for (int t = 0; t < 8; t++)
#pragma unroll
            for (int q = 0; q < 4; q++) acc[i][t][q] = 0.0f;

    const uint32_t aLd = (warp_m * 32 + (lane & 15)) * ROWB + (lane >> 4) * 16;
    const uint32_t bLd = (warp_n * 64 + ((lane >> 4) << 3) + (lane & 7)) * ROWB + (((lane >> 3) & 1) << 4);

    load_chunk(0, 0);
    for (int c = 0; c < NCH; c++) {
        if (c + 1 < NCH) load_chunk(c + 1, (c + 1) & 1);
        if (c + 1 < NCH) cp_async_wait<1>(); else cp_async_wait<0>();
        __syncthreads();
        const int s = c & 1;
#pragma unroll
        for (int kk = 0; kk < 2; kk++) {
            uint32_t a[2][4];
#pragma unroll
            for (int i = 0; i < 2; i++)
                ldsm_x4(a[i][0], a[i][1], a[i][2], a[i][3],
                        sAu[s] + aLd + i * 16 * ROWB + kk * 32);
            uint32_t b[4][4];
#pragma unroll
            for (int j = 0; j < 4; j++)
                ldsm_x4(b[j][0], b[j][1], b[j][2], b[j][3],
                        sBu[s] + bLd + j * 16 * ROWB + kk * 32);
#pragma unroll
            for (int i = 0; i < 2; i++)
#pragma unroll
                for (int t = 0; t < 8; t++)
                    mma16816(acc[i][t], a[i][0], a[i][1], a[i][2], a[i][3],
                             b[t >> 1][(t & 1) * 2], b[t >> 1][(t & 1) * 2 + 1]);
        }
        __syncthreads();
    }

    const int colBase = warp_n * 64 + (lane & 3) * 2;
#pragma unroll
    for (int i = 0; i < 2; i++) {
        int r0 = m0 + warp_m * 32 + i * 16 + (lane >> 2);
#pragma unroll
        for (int half = 0; half < 2; half++) {
            int r = r0 + half * 8;
            if (r < N_NODES) {
                float* arow = g_agg + (size_t)r * 256;
#pragma unroll
                for (int t = 0; t < 8; t++)
                    *(float2*)(arow + colBase + t * 8) =
                        make_float2(acc[i][t][half * 2], acc[i][t][half * 2 + 1]);
            }
        }
    }
}

// ---------------------------------------------------------------------------
// Epilogue: h = gelu(agg + bias + x); out = LN(h)*gamma + beta
// ---------------------------------------------------------------------------
__global__ void __launch_bounds__(256) epilogue_kernel(const float* __restrict__ x,
                                                       const float* __restrict__ bias,
                                                       const float* __restrict__ gamma,
                                                       const float* __restrict__ beta,
                                                       float* __restrict__ out) {
    int gid = blockIdx.x * blockDim.x + threadIdx.x;
    int n = gid >> 5;
    int lane = gid & 31;
    if (n >= N_NODES) return;

    const float4* arow = (const float4*)(g_agg + (size_t)n * 256);
    const float4* xrow = (const float4*)(x + (size_t)n * 256);
    float4 t0 = arow[lane], t1 = arow[lane + 32];
    float4 x0 = xrow[lane], x1 = xrow[lane + 32];
    float4 bb0 = ((const float4*)bias)[lane];
    float4 bb1 = ((const float4*)bias)[lane + 32];

    float h[8];
    h[0] = gelu_exact(t0.x + bb0.x + x0.x);
    h[1] = gelu_exact(t0.y + bb0.y + x0.y);
    h[2] = gelu_exact(t0.z + bb0.z + x0.z);
    h[3] = gelu_exact(t0.w + bb0.w + x0.w);
    h[4] = gelu_exact(t1.x + bb1.x + x1.x);
    h[5] = gelu_exact(t1.y + bb1.y + x1.y);
    h[6] = gelu_exact(t1.z + bb1.z + x1.z);
    h[7] = gelu_exact(t1.w + bb1.w + x1.w);

    float s = 0.f;
#pragma unroll
    for (int i = 0; i < 8; i++) s += h[i];
#pragma unroll
    for (int off = 16; off > 0; off >>= 1) s += __shfl_xor_sync(0xffffffffu, s, off);
    float mu = s * (1.0f / 256.0f);

    float v = 0.f;
#pragma unroll
    for (int i = 0; i < 8; i++) {
        float dlt = h[i] - mu;
        v = fmaf(dlt, dlt, v);
    }
#pragma unroll
    for (int off = 16; off > 0; off >>= 1) v += __shfl_xor_sync(0xffffffffu, v, off);
    float inv = rsqrtf(v * (1.0f / 256.0f) + 1e-5f);

    float4 g0 = ((const float4*)gamma)[lane];
    float4 g1 = ((const float4*)gamma)[lane + 32];
    float4 b0 = ((const float4*)beta)[lane];
    float4 b1 = ((const float4*)beta)[lane + 32];

    float4 o0, o1;
    o0.x = (h[0] - mu) * inv * g0.x + b0.x;
    o0.y = (h[1] - mu) * inv * g0.y + b0.y;
    o0.z = (h[2] - mu) * inv * g0.z + b0.z;
    o0.w = (h[3] - mu) * inv * g0.w + b0.w;
    o1.x = (h[4] - mu) * inv * g1.x + b1.x;
    o1.y = (h[5] - mu) * inv * g1.y + b1.y;
    o1.z = (h[6] - mu) * inv * g1.z + b1.z;
    o1.w = (h[7] - mu) * inv * g1.w + b1.w;

    float4* orow = (float4*)(out + (size_t)n * 256);
    orow[lane] = o0;
    orow[lane + 32] = o1;
}

extern "C" void kernel_launch(void* const* d_in, const int* in_sizes, int n_in,
                              void* d_out, int out_size) {
    const float* x     = (const float*)d_in[0];
    const int*   src   = (const int*)  d_in[1];
    const int*   dst   = (const int*)  d_in[2];
    const int*   et    = (const int*)  d_in[3];
    const float* basis = (const float*)d_in[4];
    const float* comp  = (const float*)d_in[5];
    const float* loopw = (const float*)d_in[6];
    const float* bias  = (const float*)d_in[7];
    const float* gamma = (const float*)d_in[8];
    const float* beta  = (const float*)d_in[9];
    float* out = (float*)d_out;

    static bool attr_set = false;
    if (!attr_set) {
        cudaFuncSetAttribute(gemm_mma_kernel, cudaFuncAttributeMaxDynamicSharedMemorySize, GEMM_SMEM);
        attr_set = true;
    }

    zero_kernel<<<(N_NODES + 255) / 256, 256>>>();
    hist_kernel<<<(N_EDGES / 8 + 255) / 256, 256>>>(dst);
    scan_kernel<<<1, 1024>>>();
    reorder_kernel<<<(N_EDGES / 8 + 255) / 256, 256>>>(src, dst, et);
    prep_b2_kernel<<<256, 256>>>(basis, loopw);
    agg_kernel<<<(N_NODES + 7) / 8, 256>>>(x, comp);
    gemm_mma_kernel<<<(N_NODES + 63) / 64, 256, GEMM_SMEM>>>();
    epilogue_kernel<<<(N_NODES * 32 + 255) / 256, 256>>>(x, bias, gamma, beta, out);
}

// round 13
// speedup vs baseline: 1.5809x; 1.0517x over previous
#include <cuda_runtime.h>
#include <cuda_fp16.h>
#include <math.h>
#include <cstdint>

#define N_NODES 20000
#define N_EDGES 640000
#define D 256
#define N_RELS 8
#define N_BASES 4
#define KA 1280              // A & B K: [T_hi(1024)|x_hi(256)]  plain fp16

// ---------------- device scratch (allocation-free rule) ----------------
__device__ __align__(16) __half g_A3[(size_t)N_NODES * KA];    // 51MB fp16
__device__ __align__(16) __half g_B2[(size_t)256 * KA];        // 0.65MB [out-col n][k]
__device__ __align__(16) __half g_xh[(size_t)N_NODES * 256];   // 10MB fp16 mirror of x
__device__ float g_agg[(size_t)N_NODES * 256];                 // 20MB (written by GEMM)
__device__ int g_hist[N_NODES];
__device__ int g_cursor[N_NODES];
__device__ int g_start[N_NODES + 1];
__device__ uint32_t g_edges[N_EDGES];   // packed src | (type<<15)

__device__ __forceinline__ float gelu_exact(float x) {
    return 0.5f * x * (1.0f + erff(x * 0.70710678118654752440f));
}
__device__ __forceinline__ uint32_t smem_to_u32(const void* p) {
    uint32_t a;
    asm("{ .reg .u64 t; cvta.to.shared.u64 t, %1; cvt.u32.u64 %0, t; }" : "=r"(a) : "l"(p));
    return a;
}
__device__ __forceinline__ void cp_async16(uint32_t dst, const void* src, int src_sz) {
    asm volatile("cp.async.cg.shared.global [%0], [%1], 16, %2;" :: "r"(dst), "l"(src), "r"(src_sz) : "memory");
}
__device__ __forceinline__ void cp_async_commit() { asm volatile("cp.async.commit_group;" ::: "memory"); }
template <int N> __device__ __forceinline__ void cp_async_wait() {
    asm volatile("cp.async.wait_group %0;" :: "n"(N) : "memory");
}
__device__ __forceinline__ void ldsm_x4(uint32_t& r0, uint32_t& r1, uint32_t& r2, uint32_t& r3, uint32_t addr) {
    asm volatile("ldmatrix.sync.aligned.m8n8.x4.shared.b16 {%0,%1,%2,%3}, [%4];"
                 : "=r"(r0), "=r"(r1), "=r"(r2), "=r"(r3) : "r"(addr));
}
__device__ __forceinline__ void mma16816(float* d, uint32_t a0, uint32_t a1, uint32_t a2, uint32_t a3,
                                         uint32_t b0, uint32_t b1) {
    asm volatile("mma.sync.aligned.m16n8k16.row.col.f32.f16.f16.f32 "
                 "{%0,%1,%2,%3}, {%4,%5,%6,%7}, {%8,%9}, {%0,%1,%2,%3};"
                 : "+f"(d[0]), "+f"(d[1]), "+f"(d[2]), "+f"(d[3])
                 : "r"(a0), "r"(a1), "r"(a2), "r"(a3), "r"(b0), "r"(b1));
}

// ---------------------------------------------------------------------------
// Prep: convert x -> fp16 mirror (4 elems/thread) and zero g_hist
// ---------------------------------------------------------------------------
__global__ void __launch_bounds__(256) prep_x_kernel(const float* __restrict__ x) {
    int gid = blockIdx.x * blockDim.x + threadIdx.x;
    if (gid < N_NODES * 64) {
        float4 v = ((const float4*)x)[gid];
        __half2 a = __halves2half2(__float2half(v.x), __float2half(v.y));
        __half2 b = __halves2half2(__float2half(v.z), __float2half(v.w));
        ((__half2*)g_xh)[gid * 2 + 0] = a;
        ((__half2*)g_xh)[gid * 2 + 1] = b;
    }
    if (gid < N_NODES) g_hist[gid] = 0;
}

// 8 edges per thread (N_EDGES % 8 == 0)
__global__ void __launch_bounds__(256) hist_kernel(const int* __restrict__ dst) {
    int g8 = (blockIdx.x * blockDim.x + threadIdx.x) * 8;
    if (g8 >= N_EDGES) return;
    int4 d0 = *(const int4*)(dst + g8);
    int4 d1 = *(const int4*)(dst + g8 + 4);
    atomicAdd(&g_hist[d0.x], 1);
    atomicAdd(&g_hist[d0.y], 1);
    atomicAdd(&g_hist[d0.z], 1);
    atomicAdd(&g_hist[d0.w], 1);
    atomicAdd(&g_hist[d1.x], 1);
    atomicAdd(&g_hist[d1.y], 1);
    atomicAdd(&g_hist[d1.z], 1);
    atomicAdd(&g_hist[d1.w], 1);
}

// single block 1024 threads, 20 bins each
__global__ void __launch_bounds__(1024) scan_kernel() {
    __shared__ int sm[1024];
    int t = threadIdx.x;
    int base = t * 20;
    int cnt[20];
    int s = 0;
#pragma unroll
    for (int i = 0; i < 20; i++) {
        int idx = base + i;
        int c = (idx < N_NODES) ? g_hist[idx] : 0;
        cnt[i] = c; s += c;
    }
    sm[t] = s;
    __syncthreads();
    for (int off = 1; off < 1024; off <<= 1) {
        int v = (t >= off) ? sm[t - off] : 0;
        __syncthreads();
        sm[t] += v;
        __syncthreads();
    }
    int run = (t > 0) ? sm[t - 1] : 0;
#pragma unroll
    for (int i = 0; i < 20; i++) {
        int idx = base + i;
        if (idx < N_NODES) {
            g_start[idx] = run;
            g_cursor[idx] = run;
            run += cnt[i];
        }
    }
    if (t == 1023) g_start[N_NODES] = sm[1023];
}

// 8 edges per thread
__global__ void __launch_bounds__(256) reorder_kernel(const int* __restrict__ src,
                                                      const int* __restrict__ dst,
                                                      const int* __restrict__ et) {
    int g8 = (blockIdx.x * blockDim.x + threadIdx.x) * 8;
    if (g8 >= N_EDGES) return;
    int4 s0 = *(const int4*)(src + g8);
    int4 s1 = *(const int4*)(src + g8 + 4);
    int4 d0 = *(const int4*)(dst + g8);
    int4 d1 = *(const int4*)(dst + g8 + 4);
    int4 t0 = *(const int4*)(et + g8);
    int4 t1 = *(const int4*)(et + g8 + 4);
    int p0 = atomicAdd(&g_cursor[d0.x], 1);
    int p1 = atomicAdd(&g_cursor[d0.y], 1);
    int p2 = atomicAdd(&g_cursor[d0.z], 1);
    int p3 = atomicAdd(&g_cursor[d0.w], 1);
    int p4 = atomicAdd(&g_cursor[d1.x], 1);
    int p5 = atomicAdd(&g_cursor[d1.y], 1);
    int p6 = atomicAdd(&g_cursor[d1.z], 1);
    int p7 = atomicAdd(&g_cursor[d1.w], 1);
    g_edges[p0] = (uint32_t)s0.x | ((uint32_t)t0.x << 15);
    g_edges[p1] = (uint32_t)s0.y | ((uint32_t)t0.y << 15);
    g_edges[p2] = (uint32_t)s0.z | ((uint32_t)t0.z << 15);
    g_edges[p3] = (uint32_t)s0.w | ((uint32_t)t0.w << 15);
    g_edges[p4] = (uint32_t)s1.x | ((uint32_t)t1.x << 15);
    g_edges[p5] = (uint32_t)s1.y | ((uint32_t)t1.y << 15);
    g_edges[p6] = (uint32_t)s1.z | ((uint32_t)t1.z << 15);
    g_edges[p7] = (uint32_t)s1.w | ((uint32_t)t1.w << 15);
}

// ---------------------------------------------------------------------------
// Prep B2 (K = 1280 fp16):
//   k<1024  : b=k>>8, i=k&255 -> fp16(basis[b][i][n])
//   k>=1024 : i=k&255         -> fp16(loop_w[i][n])
// ---------------------------------------------------------------------------
__global__ void __launch_bounds__(256) prep_b2_kernel(const float* __restrict__ basis,
                                                      const float* __restrict__ loopw) {
    int n = blockIdx.x;   // 0..255
    for (int k = threadIdx.x; k < KA; k += 256) {
        float w;
        if (k < 1024) {
            int b = k >> 8, i = k & 255;
            w = basis[(size_t)b * 65536 + (size_t)i * 256 + n];
        } else {
            int i = k & 255;
            w = loopw[(size_t)i * 256 + n];
        }
        g_B2[(size_t)n * KA + k] = __float2half(w);
    }
}

// ---------------------------------------------------------------------------
// Fused gather(fp16) + aggregate + combine: one warp per node.
// A row layout (KA=1280): [T_hi(1024)|x_hi(256)]
// ---------------------------------------------------------------------------
__device__ __forceinline__ void round8_store(__half* rowbase, int off, const float* v) {
    union { __half2 h2[4]; uint4 u; } p;
#pragma unroll
    for (int q = 0; q < 4; q++)
        p.h2[q] = __halves2half2(__float2half(v[q * 2]), __float2half(v[q * 2 + 1]));
    *(uint4*)(rowbase + off) = p.u;
}

__global__ void __launch_bounds__(256) agg_kernel(const float* __restrict__ comp) {
    __shared__ float4 cs4[N_RELS];
    int tid = threadIdx.x;
    if (tid < N_RELS)
        cs4[tid] = make_float4(comp[tid * 4 + 0], comp[tid * 4 + 1], comp[tid * 4 + 2], comp[tid * 4 + 3]);
    __syncthreads();

    int v = blockIdx.x * 8 + (tid >> 5);
    int lane = tid & 31;
    if (v >= N_NODES) return;

    int s0 = g_start[v];
    int s1 = g_start[v + 1];
    int c0 = lane * 8;

    float accT[4][8];
#pragma unroll
    for (int b = 0; b < 4; b++)
#pragma unroll
        for (int j = 0; j < 8; j++) accT[b][j] = 0.f;

    auto accum = [&](uint32_t p, uint4 xv) {
        float4 cv = cs4[p >> 15];
        const __half2* h2 = (const __half2*)&xv;
        float2 f0 = __half22float2(h2[0]);
        float2 f1 = __half22float2(h2[1]);
        float2 f2 = __half22float2(h2[2]);
        float2 f3 = __half22float2(h2[3]);
        float c;
        c = cv.x;
        accT[0][0] += c * f0.x; accT[0][1] += c * f0.y; accT[0][2] += c * f1.x; accT[0][3] += c * f1.y;
        accT[0][4] += c * f2.x; accT[0][5] += c * f2.y; accT[0][6] += c * f3.x; accT[0][7] += c * f3.y;
        c = cv.y;
        accT[1][0] += c * f0.x; accT[1][1] += c * f0.y; accT[1][2] += c * f1.x; accT[1][3] += c * f1.y;
        accT[1][4] += c * f2.x; accT[1][5] += c * f2.y; accT[1][6] += c * f3.x; accT[1][7] += c * f3.y;
        c = cv.z;
        accT[2][0] += c * f0.x; accT[2][1] += c * f0.y; accT[2][2] += c * f1.x; accT[2][3] += c * f1.y;
        accT[2][4] += c * f2.x; accT[2][5] += c * f2.y; accT[2][6] += c * f3.x; accT[2][7] += c * f3.y;
        c = cv.w;
        accT[3][0] += c * f0.x; accT[3][1] += c * f0.y; accT[3][2] += c * f1.x; accT[3][3] += c * f1.y;
        accT[3][4] += c * f2.x; accT[3][5] += c * f2.y; accT[3][6] += c * f3.x; accT[3][7] += c * f3.y;
    };

    int e = s0;
    for (; e + 4 <= s1; e += 4) {
        uint32_t p[4];
        uint4 xv[4];
#pragma unroll
        for (int j = 0; j < 4; j++) p[j] = __ldg(&g_edges[e + j]);
#pragma unroll
        for (int j = 0; j < 4; j++)
            xv[j] = *(const uint4*)(g_xh + (size_t)(p[j] & 32767) * 256 + c0);
#pragma unroll
        for (int j = 0; j < 4; j++) accum(p[j], xv[j]);
    }
    for (; e < s1; e++) {
        uint32_t p = __ldg(&g_edges[e]);
        uint4 xv = *(const uint4*)(g_xh + (size_t)(p & 32767) * 256 + c0);
        accum(p, xv);
    }

    __half* arow = g_A3 + (size_t)v * KA;
#pragma unroll
    for (int b = 0; b < 4; b++)
        round8_store(arow, b * 256 + c0, accT[b]);
    // x part: copy the already-quantized fp16 row
    *(uint4*)(arow + 1024 + c0) = *(const uint4*)(g_xh + (size_t)v * 256 + c0);
}

// ---------------------------------------------------------------------------
// GEMM: agg[20000,256] = A[20000,1280] @ B2^T   (single K pass, plain stores)
// Tile M=64, N=256, K-chunk 32, double-buffered cp.async, 256 threads.
// ---------------------------------------------------------------------------
#define KCH 32
#define NCH (KA / KCH)          // 40
#define ROWB 80
#define A_TILE (64 * ROWB)      // 5120
#define B_TILE (256 * ROWB)     // 20480
#define GEMM_SMEM (2 * A_TILE + 2 * B_TILE)   // 51200

__global__ void __launch_bounds__(256) gemm_mma_kernel() {
    extern __shared__ __align__(16) char dyn[];
    const uint32_t sAu[2] = { smem_to_u32(dyn), smem_to_u32(dyn + A_TILE) };
    const uint32_t sBu[2] = { smem_to_u32(dyn + 2 * A_TILE), smem_to_u32(dyn + 2 * A_TILE + B_TILE) };

    const int tid = threadIdx.x;
    const int lane = tid & 31;
    const int wid = tid >> 5;
    const int warp_m = wid & 1;
    const int warp_n = wid >> 1;
    const int m0 = blockIdx.x * 64;

    const int ar = tid >> 2;
    const int ac = tid & 3;
    const int am = m0 + ar;
    const int asz = (am < N_NODES) ? 16 : 0;
    const __half* aBase = g_A3 + (size_t)((am < N_NODES) ? am : 0) * KA + ac * 8;
    const uint32_t aDst = ar * ROWB + ac * 16;

    auto load_chunk = [&](int c, int s) {
        int k0 = c * KCH;
        cp_async16(sAu[s] + aDst, aBase + k0, asz);
#pragma unroll
        for (int i = 0; i < 4; i++) {
            int cid = tid + i * 256;
            int br = cid >> 2, bc = cid & 3;
            cp_async16(sBu[s] + br * ROWB + bc * 16,
                       g_B2 + (size_t)br * KA + k0 + bc * 8, 16);
        }
        cp_async_commit();
    };

    float acc[2][8][4];
#pragma unroll
    for (int i = 0; i < 2; i++)
#pragma unroll
        for (int t = 0; t < 8; t++)
#pragma unroll
            for (int q = 0; q < 4; q++) acc[i][t][q] = 0.0f;

    const uint32_t aLd = (warp_m * 32 + (lane & 15)) * ROWB + (lane >> 4) * 16;
    const uint32_t bLd = (warp_n * 64 + ((lane >> 4) << 3) + (lane & 7)) * ROWB + (((lane >> 3) & 1) << 4);

    load_chunk(0, 0);
    for (int c = 0; c < NCH; c++) {
        if (c + 1 < NCH) load_chunk(c + 1, (c + 1) & 1);
        if (c + 1 < NCH) cp_async_wait<1>(); else cp_async_wait<0>();
        __syncthreads();
        const int s = c & 1;
#pragma unroll
        for (int kk = 0; kk < 2; kk++) {
            uint32_t a[2][4];
#pragma unroll
            for (int i = 0; i < 2; i++)
                ldsm_x4(a[i][0], a[i][1], a[i][2], a[i][3],
                        sAu[s] + aLd + i * 16 * ROWB + kk * 32);
            uint32_t b[4][4];
#pragma unroll
            for (int j = 0; j < 4; j++)
                ldsm_x4(b[j][0], b[j][1], b[j][2], b[j][3],
                        sBu[s] + bLd + j * 16 * ROWB + kk * 32);
#pragma unroll
            for (int i = 0; i < 2; i++)
#pragma unroll
                for (int t = 0; t < 8; t++)
                    mma16816(acc[i][t], a[i][0], a[i][1], a[i][2], a[i][3],
                             b[t >> 1][(t & 1) * 2], b[t >> 1][(t & 1) * 2 + 1]);
        }
        __syncthreads();
    }

    const int colBase = warp_n * 64 + (lane & 3) * 2;
#pragma unroll
    for (int i = 0; i < 2; i++) {
        int r0 = m0 + warp_m * 32 + i * 16 + (lane >> 2);
#pragma unroll
        for (int half = 0; half < 2; half++) {
            int r = r0 + half * 8;
            if (r < N_NODES) {
                float* arow = g_agg + (size_t)r * 256;
#pragma unroll
                for (int t = 0; t < 8; t++)
                    *(float2*)(arow + colBase + t * 8) =
                        make_float2(acc[i][t][half * 2], acc[i][t][half * 2 + 1]);
            }
        }
    }
}

// ---------------------------------------------------------------------------
// Epilogue: h = gelu(agg + bias + x); out = LN(h)*gamma + beta
// ---------------------------------------------------------------------------
__global__ void __launch_bounds__(256) epilogue_kernel(const float* __restrict__ x,
                                                       const float* __restrict__ bias,
                                                       const float* __restrict__ gamma,
                                                       const float* __restrict__ beta,
                                                       float* __restrict__ out) {
    int gid = blockIdx.x * blockDim.x + threadIdx.x;
    int n = gid >> 5;
    int lane = gid & 31;
    if (n >= N_NODES) return;

    const float4* arow = (const float4*)(g_agg + (size_t)n * 256);
    const float4* xrow = (const float4*)(x + (size_t)n * 256);
    float4 t0 = arow[lane], t1 = arow[lane + 32];
    float4 x0 = xrow[lane], x1 = xrow[lane + 32];
    float4 bb0 = ((const float4*)bias)[lane];
    float4 bb1 = ((const float4*)bias)[lane + 32];

    float h[8];
    h[0] = gelu_exact(t0.x + bb0.x + x0.x);
    h[1] = gelu_exact(t0.y + bb0.y + x0.y);
    h[2] = gelu_exact(t0.z + bb0.z + x0.z);
    h[3] = gelu_exact(t0.w + bb0.w + x0.w);
    h[4] = gelu_exact(t1.x + bb1.x + x1.x);
    h[5] = gelu_exact(t1.y + bb1.y + x1.y);
    h[6] = gelu_exact(t1.z + bb1.z + x1.z);
    h[7] = gelu_exact(t1.w + bb1.w + x1.w);

    float s = 0.f;
#pragma unroll
    for (int i = 0; i < 8; i++) s += h[i];
#pragma unroll
    for (int off = 16; off > 0; off >>= 1) s += __shfl_xor_sync(0xffffffffu, s, off);
    float mu = s * (1.0f / 256.0f);

    float v = 0.f;
#pragma unroll
    for (int i = 0; i < 8; i++) {
        float dlt = h[i] - mu;
        v = fmaf(dlt, dlt, v);
    }
#pragma unroll
    for (int off = 16; off > 0; off >>= 1) v += __shfl_xor_sync(0xffffffffu, v, off);
    float inv = rsqrtf(v * (1.0f / 256.0f) + 1e-5f);

    float4 g0 = ((const float4*)gamma)[lane];
    float4 g1 = ((const float4*)gamma)[lane + 32];
    float4 b0 = ((const float4*)beta)[lane];
    float4 b1 = ((const float4*)beta)[lane + 32];

    float4 o0, o1;
    o0.x = (h[0] - mu) * inv * g0.x + b0.x;
    o0.y = (h[1] - mu) * inv * g0.y + b0.y;
    o0.z = (h[2] - mu) * inv * g0.z + b0.z;
    o0.w = (h[3] - mu) * inv * g0.w + b0.w;
    o1.x = (h[4] - mu) * inv * g1.x + b1.x;
    o1.y = (h[5] - mu) * inv * g1.y + b1.y;
    o1.z = (h[6] - mu) * inv * g1.z + b1.z;
    o1.w = (h[7] - mu) * inv * g1.w + b1.w;

    float4* orow = (float4*)(out + (size_t)n * 256);
    orow[lane] = o0;
    orow[lane + 32] = o1;
}

extern "C" void kernel_launch(void* const* d_in, const int* in_sizes, int n_in,
                              void* d_out, int out_size) {
    const float* x     = (const float*)d_in[0];
    const int*   src   = (const int*)  d_in[1];
    const int*   dst   = (const int*)  d_in[2];
    const int*   et    = (const int*)  d_in[3];
    const float* basis = (const float*)d_in[4];
    const float* comp  = (const float*)d_in[5];
    const float* loopw = (const float*)d_in[6];
    const float* bias  = (const float*)d_in[7];
    const float* gamma = (const float*)d_in[8];
    const float* beta  = (const float*)d_in[9];
    float* out = (float*)d_out;

    static bool attr_set = false;
    if (!attr_set) {
        cudaFuncSetAttribute(gemm_mma_kernel, cudaFuncAttributeMaxDynamicSharedMemorySize, GEMM_SMEM);
        attr_set = true;
    }

    prep_x_kernel<<<(N_NODES * 64 + 255) / 256, 256>>>(x);
    hist_kernel<<<(N_EDGES / 8 + 255) / 256, 256>>>(dst);
    scan_kernel<<<1, 1024>>>();
    reorder_kernel<<<(N_EDGES / 8 + 255) / 256, 256>>>(src, dst, et);
    prep_b2_kernel<<<256, 256>>>(basis, loopw);
    agg_kernel<<<(N_NODES + 7) / 8, 256>>>(comp);
    gemm_mma_kernel<<<(N_NODES + 63) / 64, 256, GEMM_SMEM>>>();
    epilogue_kernel<<<(N_NODES * 32 + 255) / 256, 256>>>(x, bias, gamma, beta, out);
}